// round 17
// baseline (speedup 1.0000x reference)
#include <cuda_runtime.h>
#include <cuda_fp16.h>
#include <math.h>
#include <stdint.h>

#define BB 64
#define SS 512
#define HH 1024
#define VV 50257
#define BS (BB * SS)
#define RS 80   // smem row pitch bytes (32 x 2B elems = 64B data + 16B pad)

// ======================= scratch (device globals) ===========================
__device__ float g_p[BB * HH];
__device__ float g_scores[BB * SS];
__device__ float g_context[BB * HH];
__device__ float g_x[BB * 2 * HH];
__device__ float g_gi[BB * 3 * HH];
__device__ float g_gh[BB * 3 * HH];
__device__ float g_hnew[BB * HH];
__device__ __half g_w2_h[HH * HH];      // fp16 copy of attn_w[:, H:2H]

// ======================= helpers ===========================================
__device__ __forceinline__ uint32_t smem_u32(const void* p) {
    uint32_t a;
    asm("{ .reg .u64 t; cvta.to.shared.u64 t, %1; cvt.u32.u64 %0, t; }"
        : "=r"(a) : "l"(p));
    return a;
}
__device__ __forceinline__ void ldsm4(uint32_t addr, uint32_t r[4]) {
    asm volatile("ldmatrix.sync.aligned.m8n8.x4.shared.b16 {%0,%1,%2,%3}, [%4];"
                 : "=r"(r[0]), "=r"(r[1]), "=r"(r[2]), "=r"(r[3]) : "r"(addr));
}
__device__ __forceinline__ void mma_f16(float* c, const uint32_t* a, const uint32_t* b) {
    asm volatile(
        "mma.sync.aligned.m16n8k16.row.col.f32.f16.f16.f32 "
        "{%0,%1,%2,%3}, {%4,%5,%6,%7}, {%8,%9}, {%0,%1,%2,%3};"
        : "+f"(c[0]), "+f"(c[1]), "+f"(c[2]), "+f"(c[3])
        : "r"(a[0]), "r"(a[1]), "r"(a[2]), "r"(a[3]), "r"(b[0]), "r"(b[1]));
}
// pack 8 fp32 -> 8 fp16 (uint4)
__device__ __forceinline__ uint4 cvt8h(float4 a, float4 b) {
    union { __half2 h[4]; uint4 u; } P;
    P.h[0] = __floats2half2_rn(a.x, a.y);
    P.h[1] = __floats2half2_rn(a.z, a.w);
    P.h[2] = __floats2half2_rn(b.x, b.y);
    P.h[3] = __floats2half2_rn(b.z, b.w);
    return P.u;
}
__device__ __forceinline__ float tanha(float x) {
    float e = __expf(2.f * x);
    return 1.f - __fdividef(2.f, e + 1.f);
}

// ======================= conv_w2 (fp32 -> fp16, W2 slice) ==================
__global__ void conv_w2_kernel(const float* __restrict__ attn_w) {
    size_t e = ((size_t)blockIdx.x * 256 + threadIdx.x) * 8;
    int h = (int)(e >> 10), k = (int)(e & 1023);
    const float* src = attn_w + (size_t)h * (2 * HH) + HH + k;
    float4 a = *(const float4*)src;
    float4 b = *(const float4*)(src + 4);
    *(uint4*)(g_w2_h + e) = cvt8h(a, b);
}

// ======================= zero scratch (scores + split-K accumulators) ======
__global__ void zero_scratch_kernel() {
    int i = blockIdx.x * 256 + threadIdx.x;
    if (i < BB * SS) g_scores[i] = 0.f;
    if (i < BB * HH) g_p[i] = 0.f;
    if (i < BB * 3 * HH) { g_gi[i] = 0.f; g_gh[i] = 0.f; }
}

// ======================= energy GEMM (fp16, 64x64 warp tiles) ==============
// scores[b,s] += sum_{n in tile} v[n]*tanh( p[b,n] + sum_k enc[b,s,k]*W2[n,k] )
// CTA tile 128(rows) x 256(n), KC=32, 8 warps, warp tile 64x64.
// A (enc) fp32 converted in loader; B (W2) pre-converted fp16.
__global__ void __launch_bounds__(256, 1)
attn_energy_h(const float* __restrict__ Ef,
              const __half* __restrict__ W,
              const float* __restrict__ v_w) {
    __shared__ __align__(16) char sm[128 * RS + 256 * RS];   // A, B fp16 tiles
    __shared__ float psh[256], vsh[256];
    __shared__ float red[128][4];

    const int tid = threadIdx.x, lane = tid & 31, wid = tid >> 5;
    const int n0 = blockIdx.x * 256;
    const int r0 = blockIdx.y * 128;
    const int b  = blockIdx.y >> 2;
    const int wm = wid & 1, wn = wid >> 1;   // wm 0..1 (M), wn 0..3 (N)

    psh[tid] = g_p[b * HH + n0 + tid];
    vsh[tid] = v_w[n0 + tid];

    char* smA = sm;
    char* smB = sm + 128 * RS;
    const uint32_t uA = smem_u32(smA);
    const uint32_t uB = uA + 128 * RS;

    const float*  Ab = Ef + (size_t)r0 * HH;
    const __half* Bb = W + (size_t)n0 * HH;

    // per-stage: A 128 rows x 32 fp32 (512 segs of 8), B 256 rows x 32 fp16 (1024 segs)
    float4 pa[2][2];
    uint4  pb[4];
#pragma unroll
    for (int t = 0; t < 2; t++) {
        int id = t * 256 + tid;
        int row = id >> 2, seg = id & 3;
        const float* p = Ab + (size_t)row * HH + seg * 8;
        pa[t][0] = *(const float4*)p;
        pa[t][1] = *(const float4*)(p + 4);
    }
#pragma unroll
    for (int t = 0; t < 4; t++) {
        int id = t * 256 + tid;
        int row = id >> 2, seg = id & 3;
        pb[t] = *(const uint4*)(Bb + (size_t)row * HH + seg * 8);
    }

    float acc[4][8][4];
#pragma unroll
    for (int i = 0; i < 4; i++)
#pragma unroll
        for (int j = 0; j < 8; j++)
#pragma unroll
            for (int q = 0; q < 4; q++) acc[i][j][q] = 0.f;

    for (int s = 0; s < 32; s++) {
        __syncthreads();
#pragma unroll
        for (int t = 0; t < 2; t++) {
            int id = t * 256 + tid;
            int row = id >> 2, seg = id & 3;
            *(uint4*)(smA + row * RS + seg * 16) = cvt8h(pa[t][0], pa[t][1]);
        }
#pragma unroll
        for (int t = 0; t < 4; t++) {
            int id = t * 256 + tid;
            int row = id >> 2, seg = id & 3;
            *(uint4*)(smB + row * RS + seg * 16) = pb[t];
        }
        __syncthreads();
        if (s < 31) {
            int k0 = (s + 1) * 32;
#pragma unroll
            for (int t = 0; t < 2; t++) {
                int id = t * 256 + tid;
                int row = id >> 2, seg = id & 3;
                const float* p = Ab + (size_t)row * HH + k0 + seg * 8;
                pa[t][0] = *(const float4*)p;
                pa[t][1] = *(const float4*)(p + 4);
            }
#pragma unroll
            for (int t = 0; t < 4; t++) {
                int id = t * 256 + tid;
                int row = id >> 2, seg = id & 3;
                pb[t] = *(const uint4*)(Bb + (size_t)row * HH + k0 + seg * 8);
            }
        }
#pragma unroll
        for (int ks = 0; ks < 2; ks++) {
            uint32_t ah[4][4];
#pragma unroll
            for (int mf = 0; mf < 4; mf++) {
                int row = wm * 64 + mf * 16 + (lane & 7) + ((lane >> 3) & 1) * 8;
                int kb  = ks * 32 + ((lane >> 4) & 1) * 16;
                ldsm4(uA + row * RS + kb, ah[mf]);
            }
            uint32_t bh[8][2];
#pragma unroll
            for (int np = 0; np < 4; np++) {
                int row = wn * 64 + np * 16 + ((lane >> 4) & 1) * 8 + (lane & 7);
                int kb  = ks * 32 + ((lane >> 3) & 1) * 16;
                uint32_t r4[4];
                ldsm4(uB + row * RS + kb, r4);
                bh[2*np][0] = r4[0]; bh[2*np][1] = r4[1];
                bh[2*np+1][0] = r4[2]; bh[2*np+1][1] = r4[3];
            }
#pragma unroll
            for (int mf = 0; mf < 4; mf++)
#pragma unroll
                for (int nf = 0; nf < 8; nf++)
                    mma_f16(acc[mf][nf], ah[mf], bh[nf]);
        }
    }

    // epilogue: tanh + v-weighted reduction over n
    __syncthreads();
    float sum[4][2];
#pragma unroll
    for (int mf = 0; mf < 4; mf++) { sum[mf][0] = 0.f; sum[mf][1] = 0.f; }
#pragma unroll
    for (int mf = 0; mf < 4; mf++)
#pragma unroll
        for (int nf = 0; nf < 8; nf++) {
            int n = wn * 64 + nf * 8 + (lane & 3) * 2;
            float v0 = vsh[n], v1 = vsh[n + 1];
            float p0 = psh[n], p1 = psh[n + 1];
            sum[mf][0] += v0 * tanha(acc[mf][nf][0] + p0)
                        + v1 * tanha(acc[mf][nf][1] + p1);
            sum[mf][1] += v0 * tanha(acc[mf][nf][2] + p0)
                        + v1 * tanha(acc[mf][nf][3] + p1);
        }
#pragma unroll
    for (int mf = 0; mf < 4; mf++)
#pragma unroll
        for (int half = 0; half < 2; half++) {
            float sv = sum[mf][half];
            sv += __shfl_xor_sync(0xFFFFFFFF, sv, 1);
            sv += __shfl_xor_sync(0xFFFFFFFF, sv, 2);
            if ((lane & 3) == 0) {
                int r = wm * 64 + mf * 16 + half * 8 + (lane >> 2);
                red[r][wn] = sv;
            }
        }
    __syncthreads();
    if (tid < 128)
        atomicAdd(&g_scores[r0 + tid],
                  (red[tid][0] + red[tid][1]) + (red[tid][2] + red[tid][3]));
}

// ======================= generic M=64 GEMM (fp16 single-product) ===========
// C[64,N] = bias + A[64,K] @ B[N,K]^T. fp32 inputs converted to fp16 in loader.
// grid.y = split-K slices (atomicAdd, C pre-zeroed, bias by slice 0);
// grid.y==1 -> direct store. CTA tile 64x128, warp tile 32x32.
__global__ void __launch_bounds__(256)
gemm64_h(const float* __restrict__ A, int lda,
         const float* __restrict__ Bw, int ldb,
         const float* __restrict__ bias,
         float* __restrict__ C, int N, int K) {
    __shared__ __align__(16) char sm[64 * RS + 128 * RS];   // A, B fp16

    const int tid = threadIdx.x, lane = tid & 31, wid = tid >> 5;
    const int n0 = blockIdx.x * 128;
    const int wm = wid & 1, wn = wid >> 1;
    const int nk = K / gridDim.y;
    const int kbeg = blockIdx.y * nk;

    char* smA = sm;
    char* smB = sm + 64 * RS;
    const uint32_t uA = smem_u32(smA);
    const uint32_t uB = uA + 64 * RS;

    float4 pf[3][2];
#pragma unroll
    for (int t = 0; t < 3; t++) {
        int id = t * 256 + tid;
        if (id < 256) {
            int row = id >> 2, seg = id & 3;
            const float* p = A + (size_t)row * lda + kbeg + seg * 8;
            pf[t][0] = *(const float4*)p;
            pf[t][1] = *(const float4*)(p + 4);
        } else {
            int id2 = id - 256;
            int row = id2 >> 2, seg = id2 & 3;
            int rg = n0 + row;
            if (rg < N) {
                const float* p = Bw + (size_t)rg * ldb + kbeg + seg * 8;
                pf[t][0] = *(const float4*)p;
                pf[t][1] = *(const float4*)(p + 4);
            } else {
                pf[t][0] = make_float4(0.f, 0.f, 0.f, 0.f);
                pf[t][1] = make_float4(0.f, 0.f, 0.f, 0.f);
            }
        }
    }

    float acc[2][4][4];
#pragma unroll
    for (int i = 0; i < 2; i++)
#pragma unroll
        for (int j = 0; j < 4; j++)
#pragma unroll
            for (int q = 0; q < 4; q++) acc[i][j][q] = 0.f;

    const int nstages = nk / 32;
    for (int s = 0; s < nstages; s++) {
        __syncthreads();
#pragma unroll
        for (int t = 0; t < 3; t++) {
            int id = t * 256 + tid;
            char* dst;
            int row, seg;
            if (id < 256) { row = id >> 2; seg = id & 3; dst = smA; }
            else { int id2 = id - 256; row = id2 >> 2; seg = id2 & 3; dst = smB; }
            *(uint4*)(dst + row * RS + seg * 16) = cvt8h(pf[t][0], pf[t][1]);
        }
        __syncthreads();
        if (s < nstages - 1) {
            int k0 = kbeg + (s + 1) * 32;
#pragma unroll
            for (int t = 0; t < 3; t++) {
                int id = t * 256 + tid;
                if (id < 256) {
                    int row = id >> 2, seg = id & 3;
                    const float* p = A + (size_t)row * lda + k0 + seg * 8;
                    pf[t][0] = *(const float4*)p;
                    pf[t][1] = *(const float4*)(p + 4);
                } else {
                    int id2 = id - 256;
                    int row = id2 >> 2, seg = id2 & 3;
                    int rg = n0 + row;
                    if (rg < N) {
                        const float* p = Bw + (size_t)rg * ldb + k0 + seg * 8;
                        pf[t][0] = *(const float4*)p;
                        pf[t][1] = *(const float4*)(p + 4);
                    } else {
                        pf[t][0] = make_float4(0.f, 0.f, 0.f, 0.f);
                        pf[t][1] = make_float4(0.f, 0.f, 0.f, 0.f);
                    }
                }
            }
        }
#pragma unroll
        for (int ks = 0; ks < 2; ks++) {
            uint32_t ah[2][4];
#pragma unroll
            for (int mf = 0; mf < 2; mf++) {
                int row = wm * 32 + mf * 16 + (lane & 7) + ((lane >> 3) & 1) * 8;
                int kb  = ks * 32 + ((lane >> 4) & 1) * 16;
                ldsm4(uA + row * RS + kb, ah[mf]);
            }
            uint32_t bh[4][2];
#pragma unroll
            for (int np = 0; np < 2; np++) {
                int row = wn * 32 + np * 16 + ((lane >> 4) & 1) * 8 + (lane & 7);
                int kb  = ks * 32 + ((lane >> 3) & 1) * 16;
                uint32_t r4[4];
                ldsm4(uB + row * RS + kb, r4);
                bh[2*np][0] = r4[0]; bh[2*np][1] = r4[1];
                bh[2*np+1][0] = r4[2]; bh[2*np+1][1] = r4[3];
            }
#pragma unroll
            for (int mf = 0; mf < 2; mf++)
#pragma unroll
                for (int nf = 0; nf < 4; nf++)
                    mma_f16(acc[mf][nf], ah[mf], bh[nf]);
        }
    }

    const bool direct = (gridDim.y == 1);
    const bool addb = (blockIdx.y == 0);
#pragma unroll
    for (int mf = 0; mf < 2; mf++) {
        int m = wm * 32 + mf * 16 + (lane >> 2);
#pragma unroll
        for (int nf = 0; nf < 4; nf++) {
            int n = n0 + wn * 32 + nf * 8 + (lane & 3) * 2;
            if (n < N) {
                float bb0 = addb ? bias[n] : 0.f;
                if (direct) {
                    C[(size_t)m * N + n]       = acc[mf][nf][0] + bb0;
                    C[(size_t)(m + 8) * N + n] = acc[mf][nf][2] + bb0;
                } else {
                    atomicAdd(&C[(size_t)m * N + n],       acc[mf][nf][0] + bb0);
                    atomicAdd(&C[(size_t)(m + 8) * N + n], acc[mf][nf][2] + bb0);
                }
            }
            if (n + 1 < N) {
                float bb1 = addb ? bias[n + 1] : 0.f;
                if (direct) {
                    C[(size_t)m * N + n + 1]       = acc[mf][nf][1] + bb1;
                    C[(size_t)(m + 8) * N + n + 1] = acc[mf][nf][3] + bb1;
                } else {
                    atomicAdd(&C[(size_t)m * N + n + 1],       acc[mf][nf][1] + bb1);
                    atomicAdd(&C[(size_t)(m + 8) * N + n + 1], acc[mf][nf][3] + bb1);
                }
            }
        }
    }
}

// ======================= softmax ===========================================
__global__ void softmax_kernel(float* __restrict__ attn_out) {
    int b = blockIdx.x;
    int tid = threadIdx.x;
    __shared__ float sh[256];
    float v0 = g_scores[b * SS + tid];
    float v1 = g_scores[b * SS + 256 + tid];
    float m = fmaxf(v0, v1);
    sh[tid] = m;
    __syncthreads();
    for (int o = 128; o > 0; o >>= 1) {
        if (tid < o) sh[tid] = fmaxf(sh[tid], sh[tid + o]);
        __syncthreads();
    }
    m = sh[0];
    __syncthreads();
    float e0 = expf(v0 - m), e1 = expf(v1 - m);
    sh[tid] = e0 + e1;
    __syncthreads();
    for (int o = 128; o > 0; o >>= 1) {
        if (tid < o) sh[tid] += sh[tid + o];
        __syncthreads();
    }
    float inv = 1.f / sh[0];
    attn_out[b * SS + tid]       = e0 * inv;
    attn_out[b * SS + 256 + tid] = e1 * inv;
}

// ======================= context ===========================================
__global__ void context_kernel(const float* __restrict__ enc,
                               const float* __restrict__ attn) {
    int b = blockIdx.x;
    int h = blockIdx.y * 128 + threadIdx.x;
    __shared__ float ash[SS];
    for (int i = threadIdx.x; i < SS; i += 128) ash[i] = attn[b * SS + i];
    __syncthreads();
    const float* ep = enc + (size_t)b * SS * HH + h;
    float acc = 0.f;
#pragma unroll 4
    for (int s = 0; s < SS; s++) acc += ash[s] * ep[(size_t)s * HH];
    g_context[b * HH + h] = acc;
}

// ======================= x = [emb ; context] ================================
__global__ void xbuild_kernel(const int* __restrict__ ids,
                              const float* __restrict__ emb) {
    int idx = blockIdx.x * 256 + threadIdx.x;
    int b = idx >> 11, k = idx & 2047;
    float v;
    if (k < HH) v = emb[(size_t)ids[b] * HH + k];
    else        v = g_context[b * HH + (k - HH)];
    g_x[idx] = v;
}

// ======================= GRU elementwise ====================================
__global__ void hnew_kernel(const float* __restrict__ hidden,
                            float* __restrict__ out_hidden) {
    int idx = blockIdx.x * 256 + threadIdx.x;
    int b = idx >> 10, h = idx & 1023;
    int base = b * 3 * HH;
    float ir  = g_gi[base + h];
    float iz  = g_gi[base + HH + h];
    float in_ = g_gi[base + 2 * HH + h];
    float hr  = g_gh[base + h];
    float hz  = g_gh[base + HH + h];
    float hn  = g_gh[base + 2 * HH + h];
    float r = 1.f / (1.f + expf(-(ir + hr)));
    float z = 1.f / (1.f + expf(-(iz + hz)));
    float n = tanhf(in_ + r * hn);
    float ho = hidden[idx];
    float hv = (1.f - z) * n + z * ho;
    g_hnew[idx] = hv;
    out_hidden[idx] = hv;
}

// ======================= launch =============================================
extern "C" void kernel_launch(void* const* d_in, const int* in_sizes, int n_in,
                              void* d_out, int out_size) {
    const int*   ids    = (const int*)d_in[0];
    const float* hidden = (const float*)d_in[1];
    const float* enc    = (const float*)d_in[2];
    const float* emb    = (const float*)d_in[3];
    const float* attn_w = (const float*)d_in[4];
    const float* attn_b = (const float*)d_in[5];
    const float* v_w    = (const float*)d_in[6];
    const float* w_ih   = (const float*)d_in[7];
    const float* w_hh   = (const float*)d_in[8];
    const float* b_ih   = (const float*)d_in[9];
    const float* b_hh   = (const float*)d_in[10];
    const float* out_w  = (const float*)d_in[11];
    const float* out_b  = (const float*)d_in[12];

    float* out = (float*)d_out;
    float* out_pred   = out;
    float* out_hidden = out + (size_t)BB * VV;
    float* out_attn   = out_hidden + (size_t)BB * HH;

    float *p_p, *p_x, *p_gi, *p_gh, *p_hnew;
    cudaGetSymbolAddress((void**)&p_p,    g_p);
    cudaGetSymbolAddress((void**)&p_x,    g_x);
    cudaGetSymbolAddress((void**)&p_gi,   g_gi);
    cudaGetSymbolAddress((void**)&p_gh,   g_gh);
    cudaGetSymbolAddress((void**)&p_hnew, g_hnew);
    __half* p_wh;
    cudaGetSymbolAddress((void**)&p_wh, g_w2_h);

    // 1. W2 fp16 conversion + zero split-K accumulators / scores
    conv_w2_kernel<<<(HH * HH) / 2048, 256>>>(attn_w);
    zero_scratch_kernel<<<(BB * 3 * HH) / 256, 256>>>();

    // 2. p = hidden @ W1^T + attn_b   (split-K 8; W1 = attn_w[:, :H])
    gemm64_h<<<dim3(HH / 128, 8), 256>>>(hidden, HH, attn_w, 2 * HH,
                                         attn_b, p_p, HH, HH);

    // 3. energy GEMM (fp16, 64x64 warp tiles) + fused tanh/v -> scores
    attn_energy_h<<<dim3(HH / 256, BS / 128), 256>>>(enc, p_wh, v_w);

    // 4. softmax -> attn output
    softmax_kernel<<<BB, 256>>>(out_attn);

    // 5. context = attn @ enc
    context_kernel<<<dim3(BB, HH / 128), 128>>>(enc, out_attn);

    // 6. x = [embedded ; context]
    xbuild_kernel<<<(BB * 2 * HH) / 256, 256>>>(ids, emb);

    // 7. GRU gate GEMMs (split-K 4)
    gemm64_h<<<dim3((3 * HH) / 128, 4), 256>>>(p_x, 2 * HH, w_ih, 2 * HH,
                                               b_ih, p_gi, 3 * HH, 2 * HH);
    gemm64_h<<<dim3((3 * HH) / 128, 4), 256>>>(hidden, HH, w_hh, HH,
                                               b_hh, p_gh, 3 * HH, HH);

    // 8. GRU nonlinearity -> h_new (also writes hidden output)
    hnew_kernel<<<(BB * HH) / 256, 256>>>(hidden, out_hidden);

    // 9. prediction = h_new @ out_w^T + out_b  (direct-store, out_w BW-bound)
    gemm64_h<<<dim3((VV + 127) / 128, 1), 256>>>(p_hnew, HH, out_w, HH,
                                                 out_b, out_pred, VV, HH);
}